// round 16
// baseline (speedup 1.0000x reference)
#include <cuda_runtime.h>

// Izhikevich RS constants (match reference)
#define P_A 0.02f
#define P_B 0.2f
#define P_C (-65.0f)
#define P_D 8.0f
#define I_TONIC (-3.0f)
// W_rec: diag = 4.0, offdiag = -2.0  =>  I_rec[i] = 6*r[i] - 2*sum(r)
// u' algebra: u + 0.02*(0.2 v - u) = 0.98 u + 0.004 v
// v' algebra: vn = Pq - 2*rsum, Pq = 0.04 v^2 + 6 v + (Cc - u + 6 r), Cc = 140 + Ip
// rsum recurrence: rsum' = 0.9*rsum + 0.1*nspikes (group spike count)
//
// This is the measured-best configuration (R14): dur 6.69us / ncu 5.92us,
// rel_err 0.0. Resubmitted verbatim for confirmation — R15's divide tweaks
// measured worse and are reverted.

// Warp-sum via 5-level xor butterfly (portable; f32 redux needs sm_100a which
// the harness PTX target rejects). Sum valid in all lanes.
__device__ __forceinline__ float warp_sum(float s)
{
    #pragma unroll
    for (int o = 16; o > 0; o >>= 1)
        s += __shfl_xor_sync(0xffffffffu, s, o);
    return s;
}

// One sim step, one neuron per lane (4-lane groups replicate the 4-neuron net).
// Critical path: rsum -> vn (1 fma) -> FSETP -> ballot -> popc -> magic I2F -> fma.
__device__ __forceinline__ void sim_step_lane(float& v, float& u, float& r,
                                              float& rsum, float& cnt,
                                              float Cc, unsigned gmask)
{
    // Off-critical-path (lane-local state from previous step):
    const float Pq     = fmaf(0.04f * v, v,
                              fmaf(6.0f, v, fmaf(6.0f, r, Cc - u)));
    const float rsum09 = 0.9f * rsum;
    const float un     = fmaf(0.98f, u, 0.004f * v);

    // Critical path:
    const float vn = fmaf(-2.0f, rsum, Pq);
    const bool fired = (vn >= 30.0f);
    const unsigned bal = __ballot_sync(0xffffffffu, fired);
    const int nsp = __popc(bal & gmask);
    const float fm = __uint_as_float(0x4B000000u | (unsigned)nsp); // 8388608+nsp
    const float fn = fm - 8388608.0f;                              // exact (float)nsp
    rsum = fmaf(0.1f, fn, rsum09);

    // Lane-local updates (off path):
    v = fired ? P_C : vn;
    u = fired ? (un + P_D) : un;
    r = fmaf(0.9f, r, fired ? 0.1f : 0.0f);
    cnt += fired ? 1.0f : 0.0f;
}

__global__ void __launch_bounds__(512, 1)
spiking_goal_selector_kernel(
    const float* __restrict__ pal_d_rate,   // (3072,)
    const float* __restrict__ neuromod_bias,// (4,)
    const float* __restrict__ W,            // (4, 3072) row-major
    const int*   __restrict__ substeps_p,   // scalar
    float* __restrict__ out, int out_size, int n_e)
{
    __shared__ float part[16];     // one partial per warp, float4-readable

    const int warp = threadIdx.x >> 5;
    const int lane = threadIdx.x & 31;

    // ---- hoisted scalar loads in warp 0, overlapped with the matvec wave ----
    int   T    = 0;
    float bias = 0.0f;
    if (warp == 0) {
        T    = *substeps_p;                 // broadcast LDG
        bias = neuromod_bias[lane & 3];     // broadcast per 4-lane group
    }

    // ---- matvec (measured-best config): 16 warps, 4 per row,
    //      6 fully-unrolled float4 per lane -> whole W in one load wave ----
    const int row = warp >> 2;
    const int p   = warp & 3;
    const int nv4 = n_e >> 2;
    const int q   = nv4 >> 2;          // float4s per warp-slice (192)
    const float4* Wr = reinterpret_cast<const float4*>(W + (size_t)row * n_e) + p * q;
    const float4* xr = reinterpret_cast<const float4*>(pal_d_rate) + p * q;

    float s = 0.0f;
    #pragma unroll 6
    for (int i = lane; i < q; i += 32) {
        float4 w = Wr[i];
        float4 x = xr[i];
        s += w.x * x.x + w.y * x.y + w.z * x.z + w.w * x.w;
    }
    const float wsum = warp_sum(s);
    if (lane == 0) part[warp] = wsum;
    __syncthreads();

    // ---- WTA dynamics on warp 0: one neuron per lane (lane & 3) ----
    if (warp == 0) {
        const int nl = lane & 3;
        const unsigned gmask = 0xFu << (lane & 28);

        // Per-lane prologue, serial order
        const float4* p4 = reinterpret_cast<const float4*>(part);
        float Ip[4];
        float m = 0.0f;
        #pragma unroll
        for (int j = 0; j < 4; j++) {
            const float4 v4 = p4[j];
            Ip[j] = (v4.x + v4.y) + (v4.z + v4.w);
            m += fabsf(Ip[j]);
        }
        m = m * 0.25f + 1e-8f;
        const float scale = (m > 1e-3f) ? (3.0f / m) : 0.0f;
        const float Cc = 140.0f + fmaf(Ip[nl], scale, fmaf(bias, 2.0f, I_TONIC));

        float v = P_C, u = P_B * P_C, r = 0.0f, rsum = 0.0f, cnt = 0.0f;

        if (T == 30) {
            #pragma unroll 5
            for (int t = 0; t < 30; t++)
                sim_step_lane(v, u, r, rsum, cnt, Cc, gmask);
        } else {
            for (int t = 0; t < T; t++)
                sim_step_lane(v, u, r, rsum, cnt, Cc, gmask);
        }

        // ---- epilogue: gather cnt from lanes 1..3 via independent shfls ----
        const float c1 = __shfl_sync(0xffffffffu, cnt, 1);
        const float c2 = __shfl_sync(0xffffffffu, cnt, 2);
        const float c3 = __shfl_sync(0xffffffffu, cnt, 3);

        if (lane == 0) {
            const float invT = 1.0f / (float)T;
            float4 rt;
            rt.x = cnt * invT;
            rt.y = c1  * invT;
            rt.z = c2  * invT;
            rt.w = c3  * invT;
            const float rsum2 = (rt.x + rt.y) + (rt.z + rt.w);
            int win = 0; float best = rt.x;
            if (rt.y > best) { best = rt.y; win = 1; }
            if (rt.z > best) { best = rt.z; win = 2; }
            if (rt.w > best) { best = rt.w; win = 3; }

            // Output layout: [rates(4), winner, confidence]
            if (out_size >= 6) {
                *reinterpret_cast<float4*>(out) = rt;
                out[4] = (float)win;
                out[5] = best / (rsum2 + 1e-8f);
            } else {
                const float rr[4] = {rt.x, rt.y, rt.z, rt.w};
                for (int i = 0; i < 4 && i < out_size; i++) out[i] = rr[i];
                if (out_size > 4) out[4] = (float)win;
                if (out_size > 5) out[5] = best / (rsum2 + 1e-8f);
            }
        }
    }
}

extern "C" void kernel_launch(void* const* d_in, const int* in_sizes, int n_in,
                              void* d_out, int out_size)
{
    const float* pal_d_rate    = (const float*)d_in[0];   // 3072
    const float* neuromod_bias = (const float*)d_in[1];   // 4
    const float* W_pald_goal   = (const float*)d_in[2];   // 4*3072
    const int*   substeps      = (const int*)  d_in[3];   // 1
    float* out = (float*)d_out;
    const int n_e = in_sizes[0];

    spiking_goal_selector_kernel<<<1, 512>>>(
        pal_d_rate, neuromod_bias, W_pald_goal, substeps, out, out_size, n_e);
}

// round 17
// speedup vs baseline: 1.1866x; 1.1866x over previous
#include <cuda_runtime.h>

// Izhikevich RS constants (match reference)
#define P_A 0.02f
#define P_B 0.2f
#define P_C (-65.0f)
#define P_D 8.0f
#define I_TONIC (-3.0f)
// W_rec: diag = 4.0, offdiag = -2.0  =>  I_rec[i] = 6*r[i] - 2*sum(r)
// u' algebra: u + 0.02*(0.2 v - u) = 0.98 u + 0.004 v
// v' algebra: vn = Pq - 2*rsum, Pq = 0.04 v^2 + 6 v + (Cc - u + 6 r), Cc = 140 + Ip
// rsum recurrence: rsum' = 0.9*rsum + 0.1*nspikes (group spike count)
//
// FINAL (champion) configuration. Measured best of the session:
//   dur 6.69us / ncu 5.92us, rel_err 0.0 (R14); identical binary re-measured
//   at dur 7.94 / ncu 6.14 (R16), establishing the noise band. Structural
//   wins embodied: 16-warp one-wave matvec, lane-parallel WTA sim,
//   ballot rsum recurrence, 1-fma rsum->vn critical path, small warm loop.

// Warp-sum via 5-level xor butterfly (portable; f32 redux needs sm_100a which
// the harness PTX target rejects). Sum valid in all lanes.
__device__ __forceinline__ float warp_sum(float s)
{
    #pragma unroll
    for (int o = 16; o > 0; o >>= 1)
        s += __shfl_xor_sync(0xffffffffu, s, o);
    return s;
}

// One sim step, one neuron per lane (4-lane groups replicate the 4-neuron net).
// Critical path: rsum -> vn (1 fma) -> FSETP -> ballot -> popc -> magic I2F -> fma.
__device__ __forceinline__ void sim_step_lane(float& v, float& u, float& r,
                                              float& rsum, float& cnt,
                                              float Cc, unsigned gmask)
{
    // Off-critical-path (lane-local state from previous step):
    const float Pq     = fmaf(0.04f * v, v,
                              fmaf(6.0f, v, fmaf(6.0f, r, Cc - u)));
    const float rsum09 = 0.9f * rsum;
    const float un     = fmaf(0.98f, u, 0.004f * v);

    // Critical path:
    const float vn = fmaf(-2.0f, rsum, Pq);
    const bool fired = (vn >= 30.0f);
    const unsigned bal = __ballot_sync(0xffffffffu, fired);
    const int nsp = __popc(bal & gmask);
    const float fm = __uint_as_float(0x4B000000u | (unsigned)nsp); // 8388608+nsp
    const float fn = fm - 8388608.0f;                              // exact (float)nsp
    rsum = fmaf(0.1f, fn, rsum09);

    // Lane-local updates (off path):
    v = fired ? P_C : vn;
    u = fired ? (un + P_D) : un;
    r = fmaf(0.9f, r, fired ? 0.1f : 0.0f);
    cnt += fired ? 1.0f : 0.0f;
}

__global__ void __launch_bounds__(512, 1)
spiking_goal_selector_kernel(
    const float* __restrict__ pal_d_rate,   // (3072,)
    const float* __restrict__ neuromod_bias,// (4,)
    const float* __restrict__ W,            // (4, 3072) row-major
    const int*   __restrict__ substeps_p,   // scalar
    float* __restrict__ out, int out_size, int n_e)
{
    __shared__ float part[16];     // one partial per warp, float4-readable

    const int warp = threadIdx.x >> 5;
    const int lane = threadIdx.x & 31;

    // ---- hoisted scalar loads in warp 0, overlapped with the matvec wave ----
    int   T    = 0;
    float bias = 0.0f;
    if (warp == 0) {
        T    = *substeps_p;                 // broadcast LDG
        bias = neuromod_bias[lane & 3];     // broadcast per 4-lane group
    }

    // ---- matvec (measured-best config): 16 warps, 4 per row,
    //      6 fully-unrolled float4 per lane -> whole W in one load wave ----
    const int row = warp >> 2;
    const int p   = warp & 3;
    const int nv4 = n_e >> 2;
    const int q   = nv4 >> 2;          // float4s per warp-slice (192)
    const float4* Wr = reinterpret_cast<const float4*>(W + (size_t)row * n_e) + p * q;
    const float4* xr = reinterpret_cast<const float4*>(pal_d_rate) + p * q;

    float s = 0.0f;
    #pragma unroll 6
    for (int i = lane; i < q; i += 32) {
        float4 w = Wr[i];
        float4 x = xr[i];
        s += w.x * x.x + w.y * x.y + w.z * x.z + w.w * x.w;
    }
    const float wsum = warp_sum(s);
    if (lane == 0) part[warp] = wsum;
    __syncthreads();

    // ---- WTA dynamics on warp 0: one neuron per lane (lane & 3) ----
    if (warp == 0) {
        const int nl = lane & 3;
        const unsigned gmask = 0xFu << (lane & 28);

        // Per-lane prologue, serial order
        const float4* p4 = reinterpret_cast<const float4*>(part);
        float Ip[4];
        float m = 0.0f;
        #pragma unroll
        for (int j = 0; j < 4; j++) {
            const float4 v4 = p4[j];
            Ip[j] = (v4.x + v4.y) + (v4.z + v4.w);
            m += fabsf(Ip[j]);
        }
        m = m * 0.25f + 1e-8f;
        const float scale = (m > 1e-3f) ? (3.0f / m) : 0.0f;
        const float Cc = 140.0f + fmaf(Ip[nl], scale, fmaf(bias, 2.0f, I_TONIC));

        float v = P_C, u = P_B * P_C, r = 0.0f, rsum = 0.0f, cnt = 0.0f;

        if (T == 30) {
            #pragma unroll 5
            for (int t = 0; t < 30; t++)
                sim_step_lane(v, u, r, rsum, cnt, Cc, gmask);
        } else {
            for (int t = 0; t < T; t++)
                sim_step_lane(v, u, r, rsum, cnt, Cc, gmask);
        }

        // ---- epilogue: gather cnt from lanes 1..3 via independent shfls ----
        const float c1 = __shfl_sync(0xffffffffu, cnt, 1);
        const float c2 = __shfl_sync(0xffffffffu, cnt, 2);
        const float c3 = __shfl_sync(0xffffffffu, cnt, 3);

        if (lane == 0) {
            const float invT = 1.0f / (float)T;
            float4 rt;
            rt.x = cnt * invT;
            rt.y = c1  * invT;
            rt.z = c2  * invT;
            rt.w = c3  * invT;
            const float rsum2 = (rt.x + rt.y) + (rt.z + rt.w);
            int win = 0; float best = rt.x;
            if (rt.y > best) { best = rt.y; win = 1; }
            if (rt.z > best) { best = rt.z; win = 2; }
            if (rt.w > best) { best = rt.w; win = 3; }

            // Output layout: [rates(4), winner, confidence]
            if (out_size >= 6) {
                *reinterpret_cast<float4*>(out) = rt;
                out[4] = (float)win;
                out[5] = best / (rsum2 + 1e-8f);
            } else {
                const float rr[4] = {rt.x, rt.y, rt.z, rt.w};
                for (int i = 0; i < 4 && i < out_size; i++) out[i] = rr[i];
                if (out_size > 4) out[4] = (float)win;
                if (out_size > 5) out[5] = best / (rsum2 + 1e-8f);
            }
        }
    }
}

extern "C" void kernel_launch(void* const* d_in, const int* in_sizes, int n_in,
                              void* d_out, int out_size)
{
    const float* pal_d_rate    = (const float*)d_in[0];   // 3072
    const float* neuromod_bias = (const float*)d_in[1];   // 4
    const float* W_pald_goal   = (const float*)d_in[2];   // 4*3072
    const int*   substeps      = (const int*)  d_in[3];   // 1
    float* out = (float*)d_out;
    const int n_e = in_sizes[0];

    spiking_goal_selector_kernel<<<1, 512>>>(
        pal_d_rate, neuromod_bias, W_pald_goal, substeps, out, out_size, n_e);
}